// round 7
// baseline (speedup 1.0000x reference)
#include <cuda_runtime.h>
#include <cstdint>

#define NODE_CAP 102400   // >= num_nodes (100000)
#define NBLK     1184     // 148 SMs * 8 resident blocks
#define NTHR     256

// Scratch (allocation-free). Holds sum(exp) then 1/(sum+eps).
__device__ float g_sumexp[NODE_CAP];
__device__ unsigned long long g_bar = 0;   // monotone barrier counter (replay-safe)

// ---------------- init: zero sums ----------------
__global__ void k_init() {
    int i = blockIdx.x * blockDim.x + threadIdx.x;
    if (i < NODE_CAP) g_sumexp[i] = 0.0f;
}

// Generation-based grid barrier: all NBLK blocks must be co-resident
// (guaranteed by __launch_bounds__(256,8) -> 32 regs, 0 smem).
__device__ __forceinline__ void grid_barrier() {
    __syncthreads();
    if (threadIdx.x == 0) {
        __threadfence();                                   // release prior writes
        unsigned long long old = atomicAdd(&g_bar, 1ULL);
        unsigned long long target = (old / NBLK + 1ULL) * NBLK;
        while (*(volatile unsigned long long*)&g_bar < target) { }
        __threadfence();                                   // acquire
    }
    __syncthreads();
}

// ---------------- fused: sum -> rcp -> norm ----------------
__global__ void __launch_bounds__(NTHR, 8)
k_fused(const float* __restrict__ e,
        const int* __restrict__ tgt,
        float* __restrict__ out, int n) {
    const int tid = blockIdx.x * blockDim.x + threadIdx.x;
    const int nth = NBLK * NTHR;
    const int nv  = n >> 3;          // groups of 8 edges
    const int tail = nv << 3;

    // ---- phase 1: sum of exp(e) via REDG ----
    for (int v = tid; v < nv; v += nth) {
        float4 e0 = reinterpret_cast<const float4*>(e)[2 * v];
        float4 e1 = reinterpret_cast<const float4*>(e)[2 * v + 1];
        int4   t0 = reinterpret_cast<const int4*>(tgt)[2 * v];
        int4   t1 = reinterpret_cast<const int4*>(tgt)[2 * v + 1];
        atomicAdd(&g_sumexp[t0.x], __expf(e0.x));
        atomicAdd(&g_sumexp[t0.y], __expf(e0.y));
        atomicAdd(&g_sumexp[t0.z], __expf(e0.z));
        atomicAdd(&g_sumexp[t0.w], __expf(e0.w));
        atomicAdd(&g_sumexp[t1.x], __expf(e1.x));
        atomicAdd(&g_sumexp[t1.y], __expf(e1.y));
        atomicAdd(&g_sumexp[t1.z], __expf(e1.z));
        atomicAdd(&g_sumexp[t1.w], __expf(e1.w));
    }
    for (int i = tail + tid; i < n; i += nth)
        atomicAdd(&g_sumexp[tgt[i]], __expf(e[i]));

    grid_barrier();

    // ---- phase 2: reciprocal in place ----
    for (int i = tid; i < NODE_CAP; i += nth)
        g_sumexp[i] = 1.0f / (g_sumexp[i] + 1e-16f);

    grid_barrier();

    // ---- phase 3: alpha = exp(e) * rcp[t] ----
    for (int v = tid; v < nv; v += nth) {
        float4 e0 = reinterpret_cast<const float4*>(e)[2 * v];
        float4 e1 = reinterpret_cast<const float4*>(e)[2 * v + 1];
        int4   t0 = reinterpret_cast<const int4*>(tgt)[2 * v];
        int4   t1 = reinterpret_cast<const int4*>(tgt)[2 * v + 1];
        float r0 = __ldg(&g_sumexp[t0.x]);
        float r1 = __ldg(&g_sumexp[t0.y]);
        float r2 = __ldg(&g_sumexp[t0.z]);
        float r3 = __ldg(&g_sumexp[t0.w]);
        float r4 = __ldg(&g_sumexp[t1.x]);
        float r5 = __ldg(&g_sumexp[t1.y]);
        float r6 = __ldg(&g_sumexp[t1.z]);
        float r7 = __ldg(&g_sumexp[t1.w]);
        float4 o0, o1;
        o0.x = __expf(e0.x) * r0;
        o0.y = __expf(e0.y) * r1;
        o0.z = __expf(e0.z) * r2;
        o0.w = __expf(e0.w) * r3;
        o1.x = __expf(e1.x) * r4;
        o1.y = __expf(e1.y) * r5;
        o1.z = __expf(e1.z) * r6;
        o1.w = __expf(e1.w) * r7;
        reinterpret_cast<float4*>(out)[2 * v]     = o0;
        reinterpret_cast<float4*>(out)[2 * v + 1] = o1;
    }
    for (int i = tail + tid; i < n; i += nth)
        out[i] = __expf(e[i]) * g_sumexp[tgt[i]];
}

extern "C" void kernel_launch(void* const* d_in, const int* in_sizes, int n_in,
                              void* d_out, int out_size) {
    const float* e   = (const float*)d_in[0];
    const int*   ei  = (const int*)d_in[1];   // int32 [2, n]
    float*       out = (float*)d_out;
    int n = in_sizes[0];
    const int* tgt = ei + n;  // row 1 = targets

    const int T = 256;
    int gn = (NODE_CAP + T - 1) / T;

    k_init<<<gn, T>>>();
    k_fused<<<NBLK, NTHR>>>(e, tgt, out, n);
}

// round 8
// speedup vs baseline: 1.7092x; 1.7092x over previous
#include <cuda_runtime.h>
#include <cstdint>

#define NODE_CAP 102400   // >= num_nodes (100000)

// Scratch (allocation-free). Holds sum(exp) then 1/(sum+eps).
__device__ float g_sumexp[NODE_CAP];

// ---------------- pass 1: atomic sum of exp(e), 8 edges/thread ----------------
__global__ void k_sum(const float* __restrict__ e,
                      const int* __restrict__ tgt, int n) {
    int v = blockIdx.x * blockDim.x + threadIdx.x;
    int base = v * 8;
    if (base + 7 < n) {
        float4 e0 = reinterpret_cast<const float4*>(e)[2 * v];
        float4 e1 = reinterpret_cast<const float4*>(e)[2 * v + 1];
        int4   t0 = reinterpret_cast<const int4*>(tgt)[2 * v];
        int4   t1 = reinterpret_cast<const int4*>(tgt)[2 * v + 1];
        atomicAdd(&g_sumexp[t0.x], __expf(e0.x));
        atomicAdd(&g_sumexp[t0.y], __expf(e0.y));
        atomicAdd(&g_sumexp[t0.z], __expf(e0.z));
        atomicAdd(&g_sumexp[t0.w], __expf(e0.w));
        atomicAdd(&g_sumexp[t1.x], __expf(e1.x));
        atomicAdd(&g_sumexp[t1.y], __expf(e1.y));
        atomicAdd(&g_sumexp[t1.z], __expf(e1.z));
        atomicAdd(&g_sumexp[t1.w], __expf(e1.w));
    } else {
        for (int i = base; i < n; i++)
            atomicAdd(&g_sumexp[tgt[i]], __expf(e[i]));
    }
}

// ---------------- pass 2: reciprocal in place ----------------
__global__ void k_rcp() {
    int i = blockIdx.x * blockDim.x + threadIdx.x;
    if (i < NODE_CAP) g_sumexp[i] = 1.0f / (g_sumexp[i] + 1e-16f);
}

// ---------------- pass 3: alpha = exp(e) * rcp[t], 8 edges/thread ----------------
__global__ void k_norm(const float* __restrict__ e,
                       const int* __restrict__ tgt,
                       float* __restrict__ out, int n) {
    int v = blockIdx.x * blockDim.x + threadIdx.x;
    int base = v * 8;
    if (base + 7 < n) {
        float4 e0 = reinterpret_cast<const float4*>(e)[2 * v];
        float4 e1 = reinterpret_cast<const float4*>(e)[2 * v + 1];
        int4   t0 = reinterpret_cast<const int4*>(tgt)[2 * v];
        int4   t1 = reinterpret_cast<const int4*>(tgt)[2 * v + 1];
        // Batch all gathers first so they overlap in the L1tex queue.
        float r0 = __ldg(&g_sumexp[t0.x]);
        float r1 = __ldg(&g_sumexp[t0.y]);
        float r2 = __ldg(&g_sumexp[t0.z]);
        float r3 = __ldg(&g_sumexp[t0.w]);
        float r4 = __ldg(&g_sumexp[t1.x]);
        float r5 = __ldg(&g_sumexp[t1.y]);
        float r6 = __ldg(&g_sumexp[t1.z]);
        float r7 = __ldg(&g_sumexp[t1.w]);
        float4 o0, o1;
        o0.x = __expf(e0.x) * r0;
        o0.y = __expf(e0.y) * r1;
        o0.z = __expf(e0.z) * r2;
        o0.w = __expf(e0.w) * r3;
        o1.x = __expf(e1.x) * r4;
        o1.y = __expf(e1.y) * r5;
        o1.z = __expf(e1.z) * r6;
        o1.w = __expf(e1.w) * r7;
        reinterpret_cast<float4*>(out)[2 * v]     = o0;
        reinterpret_cast<float4*>(out)[2 * v + 1] = o1;
    } else {
        for (int i = base; i < n; i++)
            out[i] = __expf(e[i]) * g_sumexp[tgt[i]];
    }
}

extern "C" void kernel_launch(void* const* d_in, const int* in_sizes, int n_in,
                              void* d_out, int out_size) {
    const float* e   = (const float*)d_in[0];
    const int*   ei  = (const int*)d_in[1];   // int32 [2, n]
    float*       out = (float*)d_out;
    int n = in_sizes[0];
    const int* tgt = ei + n;  // row 1 = targets

    // Resolve scratch symbol address once (host-side API, no allocation).
    static void* sum_ptr = nullptr;
    if (!sum_ptr) cudaGetSymbolAddress(&sum_ptr, g_sumexp);

    const int T = 512;
    int nv = (n + 7) / 8;
    int gv = (nv + T - 1) / T;
    int gn = (NODE_CAP + T - 1) / T;

    cudaMemsetAsync(sum_ptr, 0, NODE_CAP * sizeof(float));
    k_sum <<<gv, T>>>(e, tgt, n);
    k_rcp <<<gn, T>>>();
    k_norm<<<gv, T>>>(e, tgt, out, n);
}

// round 9
// speedup vs baseline: 1.7268x; 1.0103x over previous
#include <cuda_runtime.h>
#include <cstdint>

#define NODE_CAP 102400   // >= num_nodes (100000)

// Scratch (allocation-free). __device__ globals are zero-initialized at load.
// g_sumexp: accumulator — ALWAYS left zeroed at the end of each launch
// (k_rcp re-zeros it) so graph replays see a clean buffer without a memset.
__device__ float g_sumexp[NODE_CAP];
__device__ float g_rcp[NODE_CAP];

// ---------------- pass 1: atomic sum of exp(e), 8 edges/thread ----------------
__global__ void k_sum(const float* __restrict__ e,
                      const int* __restrict__ tgt, int n) {
    int v = blockIdx.x * blockDim.x + threadIdx.x;
    int base = v * 8;
    if (base + 7 < n) {
        float4 e0 = reinterpret_cast<const float4*>(e)[2 * v];
        float4 e1 = reinterpret_cast<const float4*>(e)[2 * v + 1];
        int4   t0 = reinterpret_cast<const int4*>(tgt)[2 * v];
        int4   t1 = reinterpret_cast<const int4*>(tgt)[2 * v + 1];
        atomicAdd(&g_sumexp[t0.x], __expf(e0.x));
        atomicAdd(&g_sumexp[t0.y], __expf(e0.y));
        atomicAdd(&g_sumexp[t0.z], __expf(e0.z));
        atomicAdd(&g_sumexp[t0.w], __expf(e0.w));
        atomicAdd(&g_sumexp[t1.x], __expf(e1.x));
        atomicAdd(&g_sumexp[t1.y], __expf(e1.y));
        atomicAdd(&g_sumexp[t1.z], __expf(e1.z));
        atomicAdd(&g_sumexp[t1.w], __expf(e1.w));
    } else {
        for (int i = base; i < n; i++)
            atomicAdd(&g_sumexp[tgt[i]], __expf(e[i]));
    }
}

// ---------------- pass 2: rcp into g_rcp, re-zero accumulator ----------------
__global__ void k_rcp() {
    int i = blockIdx.x * blockDim.x + threadIdx.x;
    if (i < NODE_CAP) {
        g_rcp[i] = 1.0f / (g_sumexp[i] + 1e-16f);
        g_sumexp[i] = 0.0f;   // clean for next graph replay
    }
}

// ---------------- pass 3: alpha = exp(e) * rcp[t], 8 edges/thread ----------------
__global__ void k_norm(const float* __restrict__ e,
                       const int* __restrict__ tgt,
                       float* __restrict__ out, int n) {
    int v = blockIdx.x * blockDim.x + threadIdx.x;
    int base = v * 8;
    if (base + 7 < n) {
        float4 e0 = reinterpret_cast<const float4*>(e)[2 * v];
        float4 e1 = reinterpret_cast<const float4*>(e)[2 * v + 1];
        int4   t0 = reinterpret_cast<const int4*>(tgt)[2 * v];
        int4   t1 = reinterpret_cast<const int4*>(tgt)[2 * v + 1];
        // Batch all gathers first so they overlap in the L1tex queue.
        float r0 = __ldg(&g_rcp[t0.x]);
        float r1 = __ldg(&g_rcp[t0.y]);
        float r2 = __ldg(&g_rcp[t0.z]);
        float r3 = __ldg(&g_rcp[t0.w]);
        float r4 = __ldg(&g_rcp[t1.x]);
        float r5 = __ldg(&g_rcp[t1.y]);
        float r6 = __ldg(&g_rcp[t1.z]);
        float r7 = __ldg(&g_rcp[t1.w]);
        float4 o0, o1;
        o0.x = __expf(e0.x) * r0;
        o0.y = __expf(e0.y) * r1;
        o0.z = __expf(e0.z) * r2;
        o0.w = __expf(e0.w) * r3;
        o1.x = __expf(e1.x) * r4;
        o1.y = __expf(e1.y) * r5;
        o1.z = __expf(e1.z) * r6;
        o1.w = __expf(e1.w) * r7;
        reinterpret_cast<float4*>(out)[2 * v]     = o0;
        reinterpret_cast<float4*>(out)[2 * v + 1] = o1;
    } else {
        for (int i = base; i < n; i++)
            out[i] = __expf(e[i]) * g_rcp[tgt[i]];
    }
}

extern "C" void kernel_launch(void* const* d_in, const int* in_sizes, int n_in,
                              void* d_out, int out_size) {
    const float* e   = (const float*)d_in[0];
    const int*   ei  = (const int*)d_in[1];   // int32 [2, n]
    float*       out = (float*)d_out;
    int n = in_sizes[0];
    const int* tgt = ei + n;  // row 1 = targets

    const int T = 256;
    int nv = (n + 7) / 8;
    int gv = (nv + T - 1) / T;
    int gn = (NODE_CAP + T - 1) / T;

    k_sum <<<gv, T>>>(e, tgt, n);
    k_rcp <<<gn, T>>>();
    k_norm<<<gv, T>>>(e, tgt, out, n);
}

// round 10
// speedup vs baseline: 1.7599x; 1.0192x over previous
#include <cuda_runtime.h>
#include <cstdint>

#define NODE_CAP 102400   // >= num_nodes (100000)

// Scratch (allocation-free). __device__ globals are zero-initialized at load.
// g_sumexp is ALWAYS left zeroed at the end of each launch (k_rcp re-zeros it)
// so graph replays see a clean accumulator without a memset node.
__device__ float g_sumexp[NODE_CAP];
__device__ float g_rcp[NODE_CAP];

// ---------------- pass 1: atomic sum of exp(e), 8 edges/thread, T=512 ----------------
__global__ void k_sum(const float* __restrict__ e,
                      const int* __restrict__ tgt, int n) {
    int v = blockIdx.x * blockDim.x + threadIdx.x;
    int base = v * 8;
    if (base + 7 < n) {
        float4 e0 = reinterpret_cast<const float4*>(e)[2 * v];
        float4 e1 = reinterpret_cast<const float4*>(e)[2 * v + 1];
        int4   t0 = reinterpret_cast<const int4*>(tgt)[2 * v];
        int4   t1 = reinterpret_cast<const int4*>(tgt)[2 * v + 1];
        atomicAdd(&g_sumexp[t0.x], __expf(e0.x));
        atomicAdd(&g_sumexp[t0.y], __expf(e0.y));
        atomicAdd(&g_sumexp[t0.z], __expf(e0.z));
        atomicAdd(&g_sumexp[t0.w], __expf(e0.w));
        atomicAdd(&g_sumexp[t1.x], __expf(e1.x));
        atomicAdd(&g_sumexp[t1.y], __expf(e1.y));
        atomicAdd(&g_sumexp[t1.z], __expf(e1.z));
        atomicAdd(&g_sumexp[t1.w], __expf(e1.w));
    } else {
        for (int i = base; i < n; i++)
            atomicAdd(&g_sumexp[tgt[i]], __expf(e[i]));
    }
}

// ---------------- pass 2: rcp into g_rcp, re-zero accumulator ----------------
__global__ void k_rcp() {
    int i = blockIdx.x * blockDim.x + threadIdx.x;
    if (i < NODE_CAP) {
        g_rcp[i] = 1.0f / (g_sumexp[i] + 1e-16f);
        g_sumexp[i] = 0.0f;   // clean for next graph replay
    }
}

// ---------------- pass 3: alpha = exp(e) * rcp[t], 8 edges/thread, T=256 ----------------
__global__ void k_norm(const float* __restrict__ e,
                       const int* __restrict__ tgt,
                       float* __restrict__ out, int n) {
    int v = blockIdx.x * blockDim.x + threadIdx.x;
    int base = v * 8;
    if (base + 7 < n) {
        // Last-use streaming reads: evict-first keeps the rcp table hot in L2.
        float4 e0 = __ldcs(&reinterpret_cast<const float4*>(e)[2 * v]);
        float4 e1 = __ldcs(&reinterpret_cast<const float4*>(e)[2 * v + 1]);
        int4   t0 = __ldcs(&reinterpret_cast<const int4*>(tgt)[2 * v]);
        int4   t1 = __ldcs(&reinterpret_cast<const int4*>(tgt)[2 * v + 1]);
        // Batch all gathers first so they overlap in the L1tex queue.
        float r0 = __ldg(&g_rcp[t0.x]);
        float r1 = __ldg(&g_rcp[t0.y]);
        float r2 = __ldg(&g_rcp[t0.z]);
        float r3 = __ldg(&g_rcp[t0.w]);
        float r4 = __ldg(&g_rcp[t1.x]);
        float r5 = __ldg(&g_rcp[t1.y]);
        float r6 = __ldg(&g_rcp[t1.z]);
        float r7 = __ldg(&g_rcp[t1.w]);
        float4 o0, o1;
        o0.x = __expf(e0.x) * r0;
        o0.y = __expf(e0.y) * r1;
        o0.z = __expf(e0.z) * r2;
        o0.w = __expf(e0.w) * r3;
        o1.x = __expf(e1.x) * r4;
        o1.y = __expf(e1.y) * r5;
        o1.z = __expf(e1.z) * r6;
        o1.w = __expf(e1.w) * r7;
        __stcs(&reinterpret_cast<float4*>(out)[2 * v],     o0);
        __stcs(&reinterpret_cast<float4*>(out)[2 * v + 1], o1);
    } else {
        for (int i = base; i < n; i++)
            out[i] = __expf(e[i]) * g_rcp[tgt[i]];
    }
}

extern "C" void kernel_launch(void* const* d_in, const int* in_sizes, int n_in,
                              void* d_out, int out_size) {
    const float* e   = (const float*)d_in[0];
    const int*   ei  = (const int*)d_in[1];   // int32 [2, n]
    float*       out = (float*)d_out;
    int n = in_sizes[0];
    const int* tgt = ei + n;  // row 1 = targets

    int nv = (n + 7) / 8;
    const int Ts = 512, Tn = 256;
    int gs = (nv + Ts - 1) / Ts;
    int gn = (nv + Tn - 1) / Tn;
    int gr = (NODE_CAP + Tn - 1) / Tn;

    k_sum <<<gs, Ts>>>(e, tgt, n);
    k_rcp <<<gr, Tn>>>();
    k_norm<<<gn, Tn>>>(e, tgt, out, n);
}